// round 8
// baseline (speedup 1.0000x reference)
#include <cuda_runtime.h>
#include <cstddef>

#define FULL_MASK 0xffffffffu

// ---------------------------------------------------------------------------
// packed fp32x2 FMA (sm_100+): 2x fp32 FMA throughput on Blackwell
// ---------------------------------------------------------------------------
__device__ __forceinline__ float2 ffma2(float2 a, float2 b, float2 c) {
    unsigned long long ua = *reinterpret_cast<unsigned long long*>(&a);
    unsigned long long ub = *reinterpret_cast<unsigned long long*>(&b);
    unsigned long long uc = *reinterpret_cast<unsigned long long*>(&c);
    unsigned long long ud;
    asm("fma.rn.f32x2 %0, %1, %2, %3;" : "=l"(ud) : "l"(ua), "l"(ub), "l"(uc));
    return *reinterpret_cast<float2*>(&ud);
}

// L2-coherent load: g_xg is produced by other SMs during this kernel, so it
// must NOT go through the L1/read-only path (__ldg violates its read-only
// contract here and can return stale data).
__device__ __forceinline__ float ldcg(const float* p) {
    float v;
    asm volatile("ld.global.cg.f32 %0, [%1];" : "=f"(v) : "l"(p));
    return v;
}

__device__ __forceinline__ float sigf(float x) {
    return __fdividef(1.0f, 1.0f + __expf(-x));
}
__device__ __forceinline__ float tanh_fast(float x) {
    return 2.0f * sigf(2.0f * x) - 1.0f;
}

// Scratch: precomputed layer-1 input gates XG[B*T][256]  (64 MB)
__device__ float g_xg[64 * 1024 * 256];
// Per-m-tile completion flags: y = batch*8 + chunk; ready when flag[y] == 2
__device__ int g_flag[512];

// ---------------------------------------------------------------------------
// Fused kernel. blockIdx.x < 32  -> scan CTA (batches 2b, 2b+1)
//               blockIdx.x >= 32 -> GEMM CTA (chunk-major tile order)
// ---------------------------------------------------------------------------
__global__ __launch_bounds__(256, 1) void fused_kernel(
    const float* __restrict__ X,
    const float* __restrict__ w1_ih0, const float* __restrict__ w1_hh0,
    const float* __restrict__ b1_0,
    const float* __restrict__ w1_ih1, const float* __restrict__ w1_hh1,
    const float* __restrict__ b1_1,
    const float* __restrict__ w2_ih0, const float* __restrict__ w2_hh0,
    const float* __restrict__ b2_0,
    const float* __restrict__ w2_ih1, const float* __restrict__ w2_hh1,
    const float* __restrict__ b2_1,
    const float* __restrict__ fc_w,  const float* __restrict__ fc_b,
    float* __restrict__ out)
{
    // ---------------- GEMM branch ----------------
    if (blockIdx.x >= 32) {
        __shared__ float As[16][132];
        __shared__ float Bs[16][132];
        const int gi = blockIdx.x - 32;          // 0..1023
        const int xnt = gi & 1;                  // n-tile
        const int r  = gi >> 1;                  // 0..511
        const int chunk = r >> 6;                // 0..7  (chunk-major order)
        const int batch = r & 63;
        const int y  = batch * 8 + chunk;        // m-tile id
        const int m0 = y * 128;
        const int n0 = xnt * 128;
        const int tid = threadIdx.x;
        const int tx = tid & 15;
        const int ty = tid >> 4;

        float2 c[8][4];
#pragma unroll
        for (int i = 0; i < 8; i++)
#pragma unroll
            for (int j = 0; j < 4; j++) c[i][j] = make_float2(0.f, 0.f);

        for (int k0 = 0; k0 < 512; k0 += 16) {
#pragma unroll
            for (int i = 0; i < 2; i++) {
                int idx = tid + i * 256;
                int row = idx >> 2;
                int kq  = (idx & 3) << 2;
                float4 va = *reinterpret_cast<const float4*>(&X[(size_t)(m0 + row) * 512 + k0 + kq]);
                As[kq + 0][row] = va.x; As[kq + 1][row] = va.y;
                As[kq + 2][row] = va.z; As[kq + 3][row] = va.w;
                float4 vb = *reinterpret_cast<const float4*>(&w1_ih0[(size_t)(n0 + row) * 512 + k0 + kq]);
                Bs[kq + 0][row] = vb.x; Bs[kq + 1][row] = vb.y;
                Bs[kq + 2][row] = vb.z; Bs[kq + 3][row] = vb.w;
            }
            __syncthreads();
#pragma unroll
            for (int kk = 0; kk < 16; kk++) {
                float4 a0 = *reinterpret_cast<const float4*>(&As[kk][ty * 8]);
                float4 a1 = *reinterpret_cast<const float4*>(&As[kk][ty * 8 + 4]);
                float4 b0 = *reinterpret_cast<const float4*>(&Bs[kk][tx * 8]);
                float4 b1 = *reinterpret_cast<const float4*>(&Bs[kk][tx * 8 + 4]);
                float  a[8]  = {a0.x, a0.y, a0.z, a0.w, a1.x, a1.y, a1.z, a1.w};
                float2 b2[4] = {make_float2(b0.x, b0.y), make_float2(b0.z, b0.w),
                                make_float2(b1.x, b1.y), make_float2(b1.z, b1.w)};
#pragma unroll
                for (int i = 0; i < 8; i++) {
                    float2 aa = make_float2(a[i], a[i]);
#pragma unroll
                    for (int j = 0; j < 4; j++)
                        c[i][j] = ffma2(aa, b2[j], c[i][j]);
                }
            }
            __syncthreads();
        }

        float4 bv0 = *reinterpret_cast<const float4*>(&b1_0[n0 + tx * 8]);
        float4 bv1 = *reinterpret_cast<const float4*>(&b1_0[n0 + tx * 8 + 4]);
#pragma unroll
        for (int i = 0; i < 8; i++) {
            int m = m0 + ty * 8 + i;
            float4 o0 = make_float4(c[i][0].x + bv0.x, c[i][0].y + bv0.y,
                                    c[i][1].x + bv0.z, c[i][1].y + bv0.w);
            float4 o1 = make_float4(c[i][2].x + bv1.x, c[i][2].y + bv1.y,
                                    c[i][3].x + bv1.z, c[i][3].y + bv1.w);
            *reinterpret_cast<float4*>(&g_xg[(size_t)m * 256 + n0 + tx * 8])     = o0;
            *reinterpret_cast<float4*>(&g_xg[(size_t)m * 256 + n0 + tx * 8 + 4]) = o1;
        }
        __syncthreads();
        if (tid == 0) {
            __threadfence();
            atomicAdd(&g_flag[y], 1);
        }
        return;
    }

    // ---------------- scan branch: two batches per CTA ----------------
    __shared__ float  sh_h1[2][64];
    __shared__ float  sh_h2[2][64];
    __shared__ float  sh_pre[2][256];
    __shared__ float  sh_h3[2][8];
    __shared__ float  sh_h4[2][8];
    __shared__ float2 sh_w2ih0T2[32 * 32];   // [k2][lane], lane<24 valid (shared)
    __shared__ float  sh_w2hh0T[6 * 32];     // [k][lane]
    __shared__ float  sh_w2ih1T[6 * 32];
    __shared__ float  sh_w2hh1T[6 * 32];
    __shared__ float  sh_fcw[36];            // row-major 6x6
    __shared__ float  sh_b20[32];
    __shared__ float  sh_b21[32];
    __shared__ float  sh_fcb[8];

    const int t = threadIdx.x;   // gate-vector index for layers 1 & 2
    const int bA = 2 * blockIdx.x;
    const int bB = bA + 1;

    // register-resident recurrent weights (shared by both batches)
    float2 wA[32], wB[32], wC[32];
    {
        const float2* pa = reinterpret_cast<const float2*>(w1_hh0) + t * 32;
        const float2* pb = reinterpret_cast<const float2*>(w1_ih1) + t * 32;
        const float2* pc = reinterpret_cast<const float2*>(w1_hh1) + t * 32;
#pragma unroll
        for (int i = 0; i < 32; i++) { wA[i] = pa[i]; wB[i] = pb[i]; wC[i] = pc[i]; }
    }
    const float bias11 = b1_1[t];

    // ---- init shared state / small-layer weights ----
    if (t < 64) { sh_h1[0][t] = 0.f; sh_h1[1][t] = 0.f;
                  sh_h2[0][t] = 0.f; sh_h2[1][t] = 0.f; }
    if (t < 8)  { sh_h3[0][t] = 0.f; sh_h3[1][t] = 0.f;
                  sh_h4[0][t] = 0.f; sh_h4[1][t] = 0.f;
                  sh_fcb[t] = (t < 6) ? fc_b[t] : 0.f; }
    for (int i = t; i < 1024; i += 256) {
        int k2 = i >> 5, l = i & 31;
        sh_w2ih0T2[i] = (l < 24)
            ? make_float2(w2_ih0[l * 64 + 2 * k2], w2_ih0[l * 64 + 2 * k2 + 1])
            : make_float2(0.f, 0.f);
    }
    if (t < 192) {
        int k = t / 32, l = t & 31;
        sh_w2hh0T[t] = (l < 24) ? w2_hh0[l * 6 + k] : 0.f;
        sh_w2ih1T[t] = (l < 24) ? w2_ih1[l * 6 + k] : 0.f;
        sh_w2hh1T[t] = (l < 24) ? w2_hh1[l * 6 + k] : 0.f;
    }
    if (t < 36) sh_fcw[t] = fc_w[t];
    if (t < 32) { sh_b20[t] = (t < 24) ? b2_0[t] : 0.f;
                  sh_b21[t] = (t < 24) ? b2_1[t] : 0.f; }

    // wait for chunk 0 of both batches (both n-tiles each)
    if (t == 0) {
        while (atomicAdd(&g_flag[bA * 8], 0) < 2) __nanosleep(64);
        while (atomicAdd(&g_flag[bB * 8], 0) < 2) __nanosleep(64);
        __threadfence();
    }
    __syncthreads();

    float c1[2] = {0.f, 0.f}, c2[2] = {0.f, 0.f};
    float c3 = 0.f, c4 = 0.f;     // used by warps 0/1 only (one batch each)
    const float* xg[2]  = { g_xg + ((size_t)bA << 10) * 256,
                            g_xg + ((size_t)bB << 10) * 256 };
    float*       outp[2] = { out + ((size_t)bA << 10) * 6,
                             out + ((size_t)bB << 10) * 6 };
    float xg_next[2] = { ldcg(&xg[0][t]), ldcg(&xg[1][t]) };

    for (int step = 0; step < 1024; step++) {
        // chunk-boundary gate for the prefetch of step+1
        if (((step + 1) & 127) == 0 && step < 1023) {
            if (t == 0) {
                int c = (step + 1) >> 7;
                while (atomicAdd(&g_flag[bA * 8 + c], 0) < 2) __nanosleep(64);
                while (atomicAdd(&g_flag[bB * 8 + c], 0) < 2) __nanosleep(64);
                __threadfence();
            }
            __syncthreads();
        }
        float xg_cur[2] = { xg_next[0], xg_next[1] };
        if (step < 1023) {
            xg_next[0] = ldcg(&xg[0][(size_t)(step + 1) * 256 + t]);
            xg_next[1] = ldcg(&xg[1][(size_t)(step + 1) * 256 + t]);
        }

        // --- phase 1: L1 pre-activations = Whh0 @ h1 + xg   (both batches) ---
#pragma unroll
        for (int bb = 0; bb < 2; bb++) {
            float2 acc0 = make_float2(0.f, 0.f), acc1 = make_float2(0.f, 0.f);
            const float4* hp = reinterpret_cast<const float4*>(sh_h1[bb]);
#pragma unroll
            for (int k4 = 0; k4 < 16; k4 += 2) {
                float4 ha = hp[k4];
                float4 hb = hp[k4 + 1];
                acc0 = ffma2(wA[2 * k4 + 0], make_float2(ha.x, ha.y), acc0);
                acc1 = ffma2(wA[2 * k4 + 1], make_float2(ha.z, ha.w), acc1);
                acc0 = ffma2(wA[2 * k4 + 2], make_float2(hb.x, hb.y), acc0);
                acc1 = ffma2(wA[2 * k4 + 3], make_float2(hb.z, hb.w), acc1);
            }
            sh_pre[bb][t] = acc0.x + acc0.y + acc1.x + acc1.y + xg_cur[bb];
        }
        __syncthreads();   // S1

        // --- phase 3: L1 cell (t<64) + Whh1 @ h2 partial (all), both batches ---
        float p2[2];
#pragma unroll
        for (int bb = 0; bb < 2; bb++) {
            if (t < 64) {
                float gi = sigf(sh_pre[bb][t]);
                float gf = sigf(sh_pre[bb][64 + t]);
                float gg = tanh_fast(sh_pre[bb][128 + t]);
                float go = sigf(sh_pre[bb][192 + t]);
                c1[bb] = gf * c1[bb] + gi * gg;
                sh_h1[bb][t] = go * tanh_fast(c1[bb]);
            }
            float2 acc0 = make_float2(0.f, 0.f), acc1 = make_float2(0.f, 0.f);
            const float4* hp = reinterpret_cast<const float4*>(sh_h2[bb]);
#pragma unroll
            for (int k4 = 0; k4 < 16; k4 += 2) {
                float4 ha = hp[k4];
                float4 hb = hp[k4 + 1];
                acc0 = ffma2(wC[2 * k4 + 0], make_float2(ha.x, ha.y), acc0);
                acc1 = ffma2(wC[2 * k4 + 1], make_float2(ha.z, ha.w), acc1);
                acc0 = ffma2(wC[2 * k4 + 2], make_float2(hb.x, hb.y), acc0);
                acc1 = ffma2(wC[2 * k4 + 3], make_float2(hb.z, hb.w), acc1);
            }
            p2[bb] = acc0.x + acc0.y + acc1.x + acc1.y;
        }
        __syncthreads();   // S2 (h1 new visible)

        // --- phase 5: L2 pre-activations = Wih1 @ h1_new + p2 + b ---
#pragma unroll
        for (int bb = 0; bb < 2; bb++) {
            float2 acc0 = make_float2(0.f, 0.f), acc1 = make_float2(0.f, 0.f);
            const float4* hp = reinterpret_cast<const float4*>(sh_h1[bb]);
#pragma unroll
            for (int k4 = 0; k4 < 16; k4 += 2) {
                float4 ha = hp[k4];
                float4 hb = hp[k4 + 1];
                acc0 = ffma2(wB[2 * k4 + 0], make_float2(ha.x, ha.y), acc0);
                acc1 = ffma2(wB[2 * k4 + 1], make_float2(ha.z, ha.w), acc1);
                acc0 = ffma2(wB[2 * k4 + 2], make_float2(hb.x, hb.y), acc0);
                acc1 = ffma2(wB[2 * k4 + 3], make_float2(hb.z, hb.w), acc1);
            }
            sh_pre[bb][t] = acc0.x + acc0.y + acc1.x + acc1.y + p2[bb] + bias11;
        }
        __syncthreads();   // S3

        // --- phase 7: L2 cell (t<64), both batches ---
        if (t < 64) {
#pragma unroll
            for (int bb = 0; bb < 2; bb++) {
                float gi = sigf(sh_pre[bb][t]);
                float gf = sigf(sh_pre[bb][64 + t]);
                float gg = tanh_fast(sh_pre[bb][128 + t]);
                float go = sigf(sh_pre[bb][192 + t]);
                c2[bb] = gf * c2[bb] + gi * gg;
                sh_h2[bb][t] = go * tanh_fast(c2[bb]);
            }
        }
        __syncthreads();   // S4 (h2 new visible)

        // --- tail: layers 3, 4 + FC; warp 0 -> batch A, warp 1 -> batch B ---
        if (t < 64) {
            const int bb = t >> 5;      // warp id 0/1 = batch
            const int l  = t & 31;
            // L3: gates[24] = b2_0 + W2ih0 @ h2 + W2hh0 @ h3
            float2 a0 = make_float2(0.f, 0.f), a1 = make_float2(0.f, 0.f);
            const float2* h2p = reinterpret_cast<const float2*>(sh_h2[bb]);
#pragma unroll
            for (int k2 = 0; k2 < 32; k2 += 2) {
                a0 = ffma2(sh_w2ih0T2[k2 * 32 + l],       h2p[k2],     a0);
                a1 = ffma2(sh_w2ih0T2[(k2 + 1) * 32 + l], h2p[k2 + 1], a1);
            }
            float acc = a0.x + a0.y + a1.x + a1.y + sh_b20[l];
#pragma unroll
            for (int k = 0; k < 6; k++) acc += sh_w2hh0T[k * 32 + l] * sh_h3[bb][k];
            float vf = __shfl_sync(FULL_MASK, acc, (l + 6) & 31);
            float vg = __shfl_sync(FULL_MASK, acc, (l + 12) & 31);
            float vo = __shfl_sync(FULL_MASK, acc, (l + 18) & 31);
            if (l < 6) {
                float gi = sigf(acc), gf = sigf(vf);
                float gg = tanh_fast(vg), go = sigf(vo);
                c3 = gf * c3 + gi * gg;
                sh_h3[bb][l] = go * tanh_fast(c3);
            }
            __syncwarp();
            // L4: gates[24] = b2_1 + W2ih1 @ h3 + W2hh1 @ h4
            float acc4 = sh_b21[l];
#pragma unroll
            for (int k = 0; k < 6; k++) {
                acc4 += sh_w2ih1T[k * 32 + l] * sh_h3[bb][k];
                acc4 += sh_w2hh1T[k * 32 + l] * sh_h4[bb][k];
            }
            float wf = __shfl_sync(FULL_MASK, acc4, (l + 6) & 31);
            float wg = __shfl_sync(FULL_MASK, acc4, (l + 12) & 31);
            float wo = __shfl_sync(FULL_MASK, acc4, (l + 18) & 31);
            __syncwarp();   // all reads of old sh_h4 done before overwrite
            if (l < 6) {
                float gi = sigf(acc4), gf = sigf(wf);
                float gg = tanh_fast(wg), go = sigf(wo);
                c4 = gf * c4 + gi * gg;
                sh_h4[bb][l] = go * tanh_fast(c4);
            }
            __syncwarp();
            // FC: out[6] = fc_w @ h4 + fc_b
            if (l < 6) {
                float o = sh_fcb[l];
#pragma unroll
                for (int k = 0; k < 6; k++) o += sh_fcw[l * 6 + k] * sh_h4[bb][k];
                outp[bb][(size_t)step * 6 + l] = o;
            }
        }
    }
}

// ---------------------------------------------------------------------------
extern "C" void kernel_launch(void* const* d_in, const int* in_sizes, int n_in,
                              void* d_out, int out_size) {
    const float* x      = (const float*)d_in[0];
    const float* w1_ih0 = (const float*)d_in[1];
    const float* w1_hh0 = (const float*)d_in[2];
    const float* b1_0   = (const float*)d_in[3];
    const float* w1_ih1 = (const float*)d_in[4];
    const float* w1_hh1 = (const float*)d_in[5];
    const float* b1_1   = (const float*)d_in[6];
    const float* w2_ih0 = (const float*)d_in[7];
    const float* w2_hh0 = (const float*)d_in[8];
    const float* b2_0   = (const float*)d_in[9];
    const float* w2_ih1 = (const float*)d_in[10];
    const float* w2_hh1 = (const float*)d_in[11];
    const float* b2_1   = (const float*)d_in[12];
    const float* fc_w   = (const float*)d_in[13];
    const float* fc_b   = (const float*)d_in[14];
    float* out = (float*)d_out;

    // reset GEMM-tile completion flags (graph-capturable memset node)
    void* flag_ptr = nullptr;
    cudaGetSymbolAddress(&flag_ptr, g_flag);
    cudaMemsetAsync(flag_ptr, 0, 512 * sizeof(int));

    fused_kernel<<<32 + 1024, 256>>>(x, w1_ih0, w1_hh0, b1_0,
                                     w1_ih1, w1_hh1, b1_1,
                                     w2_ih0, w2_hh0, b2_0,
                                     w2_ih1, w2_hh1, b2_1,
                                     fc_w, fc_b, out);
}

// round 9
// speedup vs baseline: 1.4352x; 1.4352x over previous
#include <cuda_runtime.h>
#include <cstddef>

#define FULL_MASK 0xffffffffu

// ---------------------------------------------------------------------------
// packed fp32x2 FMA (sm_100+)
// ---------------------------------------------------------------------------
__device__ __forceinline__ float2 ffma2(float2 a, float2 b, float2 c) {
    unsigned long long ua = *reinterpret_cast<unsigned long long*>(&a);
    unsigned long long ub = *reinterpret_cast<unsigned long long*>(&b);
    unsigned long long uc = *reinterpret_cast<unsigned long long*>(&c);
    unsigned long long ud;
    asm("fma.rn.f32x2 %0, %1, %2, %3;" : "=l"(ud) : "l"(ua), "l"(ub), "l"(uc));
    return *reinterpret_cast<float2*>(&ud);
}

// L2-coherent accessors for intra-kernel producer/consumer data.
__device__ __forceinline__ float ldcg(const float* p) {
    float v; asm volatile("ld.global.cg.f32 %0, [%1];" : "=f"(v) : "l"(p)); return v;
}
__device__ __forceinline__ float2 ldcg2(const float2* p) {
    float2 v;
    asm volatile("ld.global.cg.v2.f32 {%0,%1}, [%2];" : "=f"(v.x), "=f"(v.y) : "l"(p));
    return v;
}
__device__ __forceinline__ int ldcg_i(const int* p) {
    int v; asm volatile("ld.global.cg.s32 %0, [%1];" : "=r"(v) : "l"(p)); return v;
}
__device__ __forceinline__ void stcg(float* p, float v) {
    asm volatile("st.global.cg.f32 [%0], %1;" :: "l"(p), "f"(v));
}

__device__ __forceinline__ float sigf(float x) {
    return __fdividef(1.0f, 1.0f + __expf(-x));
}
__device__ __forceinline__ float tanh_fast(float x) {
    return 2.0f * sigf(2.0f * x) - 1.0f;
}

// Scratch
__device__ float g_xg[64 * 1024 * 256];      // layer-1 input gates (64 MB)
__device__ float g_h2[64 * 1024 * 64];       // h2 stream scan->tail (16 MB)
// flags[0..511]: GEMM m-tile (batch*8+chunk), ready at 2
// flags[512+b] : h2 stream progress for batch b (= number of steps published)
__device__ int g_flag[576];

// ---------------------------------------------------------------------------
// Fused kernel. blockIdx.x < 64    -> scan CTA (one batch, L1/L2 only)
//               blockIdx.x < 72    -> tail CTA (8 warps, one batch each: L3/L4/FC)
//               blockIdx.x >= 72   -> GEMM CTA (chunk-major tile order)
// ---------------------------------------------------------------------------
__global__ __launch_bounds__(256, 1) void fused_kernel(
    const float* __restrict__ X,
    const float* __restrict__ w1_ih0, const float* __restrict__ w1_hh0,
    const float* __restrict__ b1_0,
    const float* __restrict__ w1_ih1, const float* __restrict__ w1_hh1,
    const float* __restrict__ b1_1,
    const float* __restrict__ w2_ih0, const float* __restrict__ w2_hh0,
    const float* __restrict__ b2_0,
    const float* __restrict__ w2_ih1, const float* __restrict__ w2_hh1,
    const float* __restrict__ b2_1,
    const float* __restrict__ fc_w,  const float* __restrict__ fc_b,
    float* __restrict__ out)
{
    // ================= GEMM branch =================
    if (blockIdx.x >= 72) {
        __shared__ float As[16][132];
        __shared__ float Bs[16][132];
        const int gi = blockIdx.x - 72;          // 0..1023
        const int xnt = gi & 1;
        const int r  = gi >> 1;
        const int chunk = r >> 6;                // chunk-major order
        const int batch = r & 63;
        const int y  = batch * 8 + chunk;
        const int m0 = y * 128;
        const int n0 = xnt * 128;
        const int tid = threadIdx.x;
        const int tx = tid & 15;
        const int ty = tid >> 4;

        float2 c[8][4];
#pragma unroll
        for (int i = 0; i < 8; i++)
#pragma unroll
            for (int j = 0; j < 4; j++) c[i][j] = make_float2(0.f, 0.f);

        for (int k0 = 0; k0 < 512; k0 += 16) {
#pragma unroll
            for (int i = 0; i < 2; i++) {
                int idx = tid + i * 256;
                int row = idx >> 2;
                int kq  = (idx & 3) << 2;
                float4 va = *reinterpret_cast<const float4*>(&X[(size_t)(m0 + row) * 512 + k0 + kq]);
                As[kq + 0][row] = va.x; As[kq + 1][row] = va.y;
                As[kq + 2][row] = va.z; As[kq + 3][row] = va.w;
                float4 vb = *reinterpret_cast<const float4*>(&w1_ih0[(size_t)(n0 + row) * 512 + k0 + kq]);
                Bs[kq + 0][row] = vb.x; Bs[kq + 1][row] = vb.y;
                Bs[kq + 2][row] = vb.z; Bs[kq + 3][row] = vb.w;
            }
            __syncthreads();
#pragma unroll
            for (int kk = 0; kk < 16; kk++) {
                float4 a0 = *reinterpret_cast<const float4*>(&As[kk][ty * 8]);
                float4 a1 = *reinterpret_cast<const float4*>(&As[kk][ty * 8 + 4]);
                float4 b0 = *reinterpret_cast<const float4*>(&Bs[kk][tx * 8]);
                float4 b1 = *reinterpret_cast<const float4*>(&Bs[kk][tx * 8 + 4]);
                float  a[8]  = {a0.x, a0.y, a0.z, a0.w, a1.x, a1.y, a1.z, a1.w};
                float2 b2[4] = {make_float2(b0.x, b0.y), make_float2(b0.z, b0.w),
                                make_float2(b1.x, b1.y), make_float2(b1.z, b1.w)};
#pragma unroll
                for (int i = 0; i < 8; i++) {
                    float2 aa = make_float2(a[i], a[i]);
#pragma unroll
                    for (int j = 0; j < 4; j++)
                        c[i][j] = ffma2(aa, b2[j], c[i][j]);
                }
            }
            __syncthreads();
        }

        float4 bv0 = *reinterpret_cast<const float4*>(&b1_0[n0 + tx * 8]);
        float4 bv1 = *reinterpret_cast<const float4*>(&b1_0[n0 + tx * 8 + 4]);
#pragma unroll
        for (int i = 0; i < 8; i++) {
            int m = m0 + ty * 8 + i;
            float4 o0 = make_float4(c[i][0].x + bv0.x, c[i][0].y + bv0.y,
                                    c[i][1].x + bv0.z, c[i][1].y + bv0.w);
            float4 o1 = make_float4(c[i][2].x + bv1.x, c[i][2].y + bv1.y,
                                    c[i][3].x + bv1.z, c[i][3].y + bv1.w);
            *reinterpret_cast<float4*>(&g_xg[(size_t)m * 256 + n0 + tx * 8])     = o0;
            *reinterpret_cast<float4*>(&g_xg[(size_t)m * 256 + n0 + tx * 8 + 4]) = o1;
        }
        __syncthreads();
        if (tid == 0) {
            __threadfence();
            atomicAdd(&g_flag[y], 1);
        }
        return;
    }

    // ================= tail branch: L3/L4/FC, one batch per warp =================
    if (blockIdx.x >= 64) {
        __shared__ float2 tw_ih0[32 * 32];      // [k2][lane], lane<24 valid
        __shared__ float  tw_hh0[6 * 32];       // [k][lane]
        __shared__ float  tw_ih1[6 * 32];
        __shared__ float  tw_hh1[6 * 32];
        __shared__ float  tfcw[36];
        __shared__ float  tb20[32];
        __shared__ float  tb21[32];
        __shared__ float  tfcb[8];
        __shared__ float  th3[8][8];
        __shared__ float  th4[8][8];
        __shared__ float2 th2[8][32];

        const int t = threadIdx.x;
        for (int i = t; i < 1024; i += 256) {
            int k2 = i >> 5, l = i & 31;
            tw_ih0[i] = (l < 24)
                ? make_float2(w2_ih0[l * 64 + 2 * k2], w2_ih0[l * 64 + 2 * k2 + 1])
                : make_float2(0.f, 0.f);
        }
        if (t < 192) {
            int k = t / 32, l = t & 31;
            tw_hh0[t] = (l < 24) ? w2_hh0[l * 6 + k] : 0.f;
            tw_ih1[t] = (l < 24) ? w2_ih1[l * 6 + k] : 0.f;
            tw_hh1[t] = (l < 24) ? w2_hh1[l * 6 + k] : 0.f;
        }
        if (t < 36) tfcw[t] = fc_w[t];
        if (t < 32) { tb20[t] = (t < 24) ? b2_0[t] : 0.f;
                      tb21[t] = (t < 24) ? b2_1[t] : 0.f; }
        if (t < 8)  tfcb[t] = (t < 6) ? fc_b[t] : 0.f;
        if (t < 64) { th3[t >> 3][t & 7] = 0.f; th4[t >> 3][t & 7] = 0.f; }
        __syncthreads();

        const int w = t >> 5;                 // warp -> batch slot
        const int l = t & 31;
        const int b = (blockIdx.x - 64) * 8 + w;
        const int* flg = &g_flag[512 + b];
        float c3 = 0.f, c4 = 0.f;
        float* outp = out + ((size_t)b << 10) * 6;

        for (int s = 0; s < 1024; s++) {
            // acquire h2(s)
            while (ldcg_i(flg) < s + 1) __nanosleep(100);
            __threadfence();
            th2[w][l] = ldcg2(reinterpret_cast<const float2*>(
                                 &g_h2[((size_t)b * 1024 + s) * 64]) + l);
            __syncwarp();

            // L3: gates[24] = b2_0 + W2ih0 @ h2 + W2hh0 @ h3
            const float2* h2p = th2[w];
            float2 a0 = make_float2(0.f, 0.f), a1 = make_float2(0.f, 0.f);
#pragma unroll
            for (int k2 = 0; k2 < 32; k2 += 2) {
                a0 = ffma2(tw_ih0[k2 * 32 + l],       h2p[k2],     a0);
                a1 = ffma2(tw_ih0[(k2 + 1) * 32 + l], h2p[k2 + 1], a1);
            }
            float acc = a0.x + a0.y + a1.x + a1.y + tb20[l];
#pragma unroll
            for (int k = 0; k < 6; k++) acc += tw_hh0[k * 32 + l] * th3[w][k];
            float vf = __shfl_sync(FULL_MASK, acc, (l + 6) & 31);
            float vg = __shfl_sync(FULL_MASK, acc, (l + 12) & 31);
            float vo = __shfl_sync(FULL_MASK, acc, (l + 18) & 31);
            if (l < 6) {
                float gi = sigf(acc), gf = sigf(vf);
                float gg = tanh_fast(vg), go = sigf(vo);
                c3 = gf * c3 + gi * gg;
                th3[w][l] = go * tanh_fast(c3);
            }
            __syncwarp();
            // L4
            float acc4 = tb21[l];
#pragma unroll
            for (int k = 0; k < 6; k++) {
                acc4 += tw_ih1[k * 32 + l] * th3[w][k];
                acc4 += tw_hh1[k * 32 + l] * th4[w][k];
            }
            float wf = __shfl_sync(FULL_MASK, acc4, (l + 6) & 31);
            float wg = __shfl_sync(FULL_MASK, acc4, (l + 12) & 31);
            float wo = __shfl_sync(FULL_MASK, acc4, (l + 18) & 31);
            __syncwarp();
            if (l < 6) {
                float gi = sigf(acc4), gf = sigf(wf);
                float gg = tanh_fast(wg), go = sigf(wo);
                c4 = gf * c4 + gi * gg;
                th4[w][l] = go * tanh_fast(c4);
            }
            __syncwarp();
            if (l < 6) {
                float o = tfcb[l];
#pragma unroll
                for (int k = 0; k < 6; k++) o += tfcw[l * 6 + k] * th4[w][k];
                outp[(size_t)s * 6 + l] = o;
            }
        }
        return;
    }

    // ================= scan branch: L1/L2 only, 3 barriers/step =================
    __shared__ float sh_h1[64];
    __shared__ float sh_h2[64];
    __shared__ float sh_pre[2][256];     // double-buffered by step parity

    const int t = threadIdx.x;
    const int b = blockIdx.x;
    const int yb = b * 8;

    float2 wA[32], wB[32], wC[32];
    {
        const float2* pa = reinterpret_cast<const float2*>(w1_hh0) + t * 32;
        const float2* pb = reinterpret_cast<const float2*>(w1_ih1) + t * 32;
        const float2* pc = reinterpret_cast<const float2*>(w1_hh1) + t * 32;
#pragma unroll
        for (int i = 0; i < 32; i++) { wA[i] = pa[i]; wB[i] = pb[i]; wC[i] = pc[i]; }
    }
    const float bias11 = b1_1[t];

    if (t < 64) { sh_h1[t] = 0.f; sh_h2[t] = 0.f; }

    // wait for chunk 0
    if (t == 0) {
        while (atomicAdd(&g_flag[yb], 0) < 2) __nanosleep(64);
        __threadfence();
    }
    __syncthreads();

    float c1 = 0.f, c2 = 0.f;
    const float* xg = g_xg + ((size_t)b << 10) * 256;
    float xg_next = ldcg(&xg[t]);

    for (int step = 0; step < 1024; step++) {
        const int pr = step & 1;

        if (((step + 1) & 127) == 0 && step < 1023) {
            if (t == 0) {
                int yc = yb + ((step + 1) >> 7);
                while (atomicAdd(&g_flag[yc], 0) < 2) __nanosleep(64);
                __threadfence();
            }
            __syncthreads();
        }
        float xg_cur = xg_next;
        if (step < 1023) xg_next = ldcg(&xg[(size_t)(step + 1) * 256 + t]);

        // --- P1: L1 pre-activations = Whh0 @ h1 + xg ---
        {
            float2 acc0 = make_float2(0.f, 0.f), acc1 = make_float2(0.f, 0.f);
            const float4* hp = reinterpret_cast<const float4*>(sh_h1);
#pragma unroll
            for (int k4 = 0; k4 < 16; k4 += 2) {
                float4 ha = hp[k4];
                float4 hb = hp[k4 + 1];
                acc0 = ffma2(wA[2 * k4 + 0], make_float2(ha.x, ha.y), acc0);
                acc1 = ffma2(wA[2 * k4 + 1], make_float2(ha.z, ha.w), acc1);
                acc0 = ffma2(wA[2 * k4 + 2], make_float2(hb.x, hb.y), acc0);
                acc1 = ffma2(wA[2 * k4 + 3], make_float2(hb.z, hb.w), acc1);
            }
            sh_pre[pr][t] = acc0.x + acc0.y + acc1.x + acc1.y + xg_cur;
        }
        __syncthreads();   // S1  (also orders h2(step-1) STGs for publish below)

        // publish h2(step-1) to tail consumers
        if (t == 0 && step > 0) {
            __threadfence();
            atomicMax(&g_flag[512 + b], step);
        }

        // --- P3: L1 cell (t<64) + Whh1 @ h2 partial (all) ---
        float p2;
        {
            if (t < 64) {
                float gi = sigf(sh_pre[pr][t]);
                float gf = sigf(sh_pre[pr][64 + t]);
                float gg = tanh_fast(sh_pre[pr][128 + t]);
                float go = sigf(sh_pre[pr][192 + t]);
                c1 = gf * c1 + gi * gg;
                sh_h1[t] = go * tanh_fast(c1);
            }
            float2 acc0 = make_float2(0.f, 0.f), acc1 = make_float2(0.f, 0.f);
            const float4* hp = reinterpret_cast<const float4*>(sh_h2);
#pragma unroll
            for (int k4 = 0; k4 < 16; k4 += 2) {
                float4 ha = hp[k4];
                float4 hb = hp[k4 + 1];
                acc0 = ffma2(wC[2 * k4 + 0], make_float2(ha.x, ha.y), acc0);
                acc1 = ffma2(wC[2 * k4 + 1], make_float2(ha.z, ha.w), acc1);
                acc0 = ffma2(wC[2 * k4 + 2], make_float2(hb.x, hb.y), acc0);
                acc1 = ffma2(wC[2 * k4 + 3], make_float2(hb.z, hb.w), acc1);
            }
            p2 = acc0.x + acc0.y + acc1.x + acc1.y;
        }
        __syncthreads();   // S2 (h1 new visible)

        // --- P5: L2 pre-activations = Wih1 @ h1_new + p2 + b ---
        {
            float2 acc0 = make_float2(0.f, 0.f), acc1 = make_float2(0.f, 0.f);
            const float4* hp = reinterpret_cast<const float4*>(sh_h1);
#pragma unroll
            for (int k4 = 0; k4 < 16; k4 += 2) {
                float4 ha = hp[k4];
                float4 hb = hp[k4 + 1];
                acc0 = ffma2(wB[2 * k4 + 0], make_float2(ha.x, ha.y), acc0);
                acc1 = ffma2(wB[2 * k4 + 1], make_float2(ha.z, ha.w), acc1);
                acc0 = ffma2(wB[2 * k4 + 2], make_float2(hb.x, hb.y), acc0);
                acc1 = ffma2(wB[2 * k4 + 3], make_float2(hb.z, hb.w), acc1);
            }
            sh_pre[pr][t] = acc0.x + acc0.y + acc1.x + acc1.y + p2 + bias11;
        }
        __syncthreads();   // S3

        // --- P7: L2 cell (t<64); overlaps next step's P1 (no barrier) ---
        if (t < 64) {
            float gi = sigf(sh_pre[pr][t]);
            float gf = sigf(sh_pre[pr][64 + t]);
            float gg = tanh_fast(sh_pre[pr][128 + t]);
            float go = sigf(sh_pre[pr][192 + t]);
            c2 = gf * c2 + gi * gg;
            float h2n = go * tanh_fast(c2);
            sh_h2[t] = h2n;
            stcg(&g_h2[((size_t)b * 1024 + step) * 64 + t], h2n);
        }
        // no S4: P1' writes sh_pre[pr^1], reads sh_h1 only; S1' orders h2.
    }
    __syncthreads();
    if (t == 0) {
        __threadfence();
        atomicMax(&g_flag[512 + b], 1024);
    }
}

// ---------------------------------------------------------------------------
extern "C" void kernel_launch(void* const* d_in, const int* in_sizes, int n_in,
                              void* d_out, int out_size) {
    const float* x      = (const float*)d_in[0];
    const float* w1_ih0 = (const float*)d_in[1];
    const float* w1_hh0 = (const float*)d_in[2];
    const float* b1_0   = (const float*)d_in[3];
    const float* w1_ih1 = (const float*)d_in[4];
    const float* w1_hh1 = (const float*)d_in[5];
    const float* b1_1   = (const float*)d_in[6];
    const float* w2_ih0 = (const float*)d_in[7];
    const float* w2_hh0 = (const float*)d_in[8];
    const float* b2_0   = (const float*)d_in[9];
    const float* w2_ih1 = (const float*)d_in[10];
    const float* w2_hh1 = (const float*)d_in[11];
    const float* b2_1   = (const float*)d_in[12];
    const float* fc_w   = (const float*)d_in[13];
    const float* fc_b   = (const float*)d_in[14];
    float* out = (float*)d_out;

    // reset completion flags (graph-capturable memset node)
    void* flag_ptr = nullptr;
    cudaGetSymbolAddress(&flag_ptr, g_flag);
    cudaMemsetAsync(flag_ptr, 0, 576 * sizeof(int));

    fused_kernel<<<72 + 1024, 256>>>(x, w1_ih0, w1_hh0, b1_0,
                                     w1_ih1, w1_hh1, b1_1,
                                     w2_ih0, w2_hh0, b2_0,
                                     w2_ih1, w2_hh1, b2_1,
                                     fc_w, fc_b, out);
}

// round 10
// speedup vs baseline: 1.4427x; 1.0052x over previous
#include <cuda_runtime.h>
#include <cstddef>

#define FULL_MASK 0xffffffffu

// ---------------------------------------------------------------------------
// packed fp32x2 FMA (sm_100+)
// ---------------------------------------------------------------------------
__device__ __forceinline__ float2 ffma2(float2 a, float2 b, float2 c) {
    unsigned long long ua = *reinterpret_cast<unsigned long long*>(&a);
    unsigned long long ub = *reinterpret_cast<unsigned long long*>(&b);
    unsigned long long uc = *reinterpret_cast<unsigned long long*>(&c);
    unsigned long long ud;
    asm("fma.rn.f32x2 %0, %1, %2, %3;" : "=l"(ud) : "l"(ua), "l"(ub), "l"(uc));
    return *reinterpret_cast<float2*>(&ud);
}

// L2-coherent accessors for intra-kernel producer/consumer data.
__device__ __forceinline__ float ldcg(const float* p) {
    float v; asm volatile("ld.global.cg.f32 %0, [%1];" : "=f"(v) : "l"(p)); return v;
}
__device__ __forceinline__ float2 ldcg2(const float2* p) {
    float2 v;
    asm volatile("ld.global.cg.v2.f32 {%0,%1}, [%2];" : "=f"(v.x), "=f"(v.y) : "l"(p));
    return v;
}
__device__ __forceinline__ int ldcg_i(const int* p) {
    int v; asm volatile("ld.global.cg.s32 %0, [%1];" : "=r"(v) : "l"(p)); return v;
}
__device__ __forceinline__ void stcg(float* p, float v) {
    asm volatile("st.global.cg.f32 [%0], %1;" :: "l"(p), "f"(v));
}

__device__ __forceinline__ float sigf(float x) {
    return __fdividef(1.0f, 1.0f + __expf(-x));
}
__device__ __forceinline__ float tanh_fast(float x) {
    return 2.0f * sigf(2.0f * x) - 1.0f;
}

// Scratch
__device__ float g_xg[64 * 1024 * 256];      // layer-1 input gates (64 MB)
__device__ float g_h2[64 * 1024 * 64];       // h2 stream scan->tail (16 MB)
// flags[0..511]: GEMM m-tile (batch*8+chunk), ready at 2
// flags[512+b] : h2 stream progress for batch b (= number of steps published)
__device__ int g_flag[576];

// ---------------------------------------------------------------------------
// Fused kernel. blockIdx.x < 64    -> scan CTA (one batch, L1/L2 only)
//               blockIdx.x < 72    -> tail CTA (8 warps, one batch each: L3/L4/FC)
//               blockIdx.x >= 72   -> GEMM CTA (chunk-major tile order)
// ---------------------------------------------------------------------------
__global__ __launch_bounds__(256, 1) void fused_kernel(
    const float* __restrict__ X,
    const float* __restrict__ w1_ih0, const float* __restrict__ w1_hh0,
    const float* __restrict__ b1_0,
    const float* __restrict__ w1_ih1, const float* __restrict__ w1_hh1,
    const float* __restrict__ b1_1,
    const float* __restrict__ w2_ih0, const float* __restrict__ w2_hh0,
    const float* __restrict__ b2_0,
    const float* __restrict__ w2_ih1, const float* __restrict__ w2_hh1,
    const float* __restrict__ b2_1,
    const float* __restrict__ fc_w,  const float* __restrict__ fc_b,
    float* __restrict__ out)
{
    // ================= GEMM branch =================
    if (blockIdx.x >= 72) {
        __shared__ float As[16][132];
        __shared__ float Bs[16][132];
        const int gi = blockIdx.x - 72;          // 0..1023
        const int xnt = gi & 1;
        const int r  = gi >> 1;
        const int chunk = r >> 6;                // chunk-major order
        const int batch = r & 63;
        const int y  = batch * 8 + chunk;
        const int m0 = y * 128;
        const int n0 = xnt * 128;
        const int tid = threadIdx.x;
        const int tx = tid & 15;
        const int ty = tid >> 4;

        float2 c[8][4];
#pragma unroll
        for (int i = 0; i < 8; i++)
#pragma unroll
            for (int j = 0; j < 4; j++) c[i][j] = make_float2(0.f, 0.f);

        for (int k0 = 0; k0 < 512; k0 += 16) {
#pragma unroll
            for (int i = 0; i < 2; i++) {
                int idx = tid + i * 256;
                int row = idx >> 2;
                int kq  = (idx & 3) << 2;
                float4 va = *reinterpret_cast<const float4*>(&X[(size_t)(m0 + row) * 512 + k0 + kq]);
                As[kq + 0][row] = va.x; As[kq + 1][row] = va.y;
                As[kq + 2][row] = va.z; As[kq + 3][row] = va.w;
                float4 vb = *reinterpret_cast<const float4*>(&w1_ih0[(size_t)(n0 + row) * 512 + k0 + kq]);
                Bs[kq + 0][row] = vb.x; Bs[kq + 1][row] = vb.y;
                Bs[kq + 2][row] = vb.z; Bs[kq + 3][row] = vb.w;
            }
            __syncthreads();
#pragma unroll
            for (int kk = 0; kk < 16; kk++) {
                float4 a0 = *reinterpret_cast<const float4*>(&As[kk][ty * 8]);
                float4 a1 = *reinterpret_cast<const float4*>(&As[kk][ty * 8 + 4]);
                float4 b0 = *reinterpret_cast<const float4*>(&Bs[kk][tx * 8]);
                float4 b1 = *reinterpret_cast<const float4*>(&Bs[kk][tx * 8 + 4]);
                float  a[8]  = {a0.x, a0.y, a0.z, a0.w, a1.x, a1.y, a1.z, a1.w};
                float2 b2[4] = {make_float2(b0.x, b0.y), make_float2(b0.z, b0.w),
                                make_float2(b1.x, b1.y), make_float2(b1.z, b1.w)};
#pragma unroll
                for (int i = 0; i < 8; i++) {
                    float2 aa = make_float2(a[i], a[i]);
#pragma unroll
                    for (int j = 0; j < 4; j++)
                        c[i][j] = ffma2(aa, b2[j], c[i][j]);
                }
            }
            __syncthreads();
        }

        float4 bv0 = *reinterpret_cast<const float4*>(&b1_0[n0 + tx * 8]);
        float4 bv1 = *reinterpret_cast<const float4*>(&b1_0[n0 + tx * 8 + 4]);
#pragma unroll
        for (int i = 0; i < 8; i++) {
            int m = m0 + ty * 8 + i;
            float4 o0 = make_float4(c[i][0].x + bv0.x, c[i][0].y + bv0.y,
                                    c[i][1].x + bv0.z, c[i][1].y + bv0.w);
            float4 o1 = make_float4(c[i][2].x + bv1.x, c[i][2].y + bv1.y,
                                    c[i][3].x + bv1.z, c[i][3].y + bv1.w);
            *reinterpret_cast<float4*>(&g_xg[(size_t)m * 256 + n0 + tx * 8])     = o0;
            *reinterpret_cast<float4*>(&g_xg[(size_t)m * 256 + n0 + tx * 8 + 4]) = o1;
        }
        __syncthreads();
        if (tid == 0) {
            __threadfence();
            atomicAdd(&g_flag[y], 1);
        }
        return;
    }

    // ================= tail branch: L3/L4/FC, one batch per warp =================
    if (blockIdx.x >= 64) {
        __shared__ float2 tw_ih0[32 * 32];      // [k2][lane], lane<24 valid
        __shared__ float  tw_hh0[6 * 32];       // [k][lane]
        __shared__ float  tw_ih1[6 * 32];
        __shared__ float  tw_hh1[6 * 32];
        __shared__ float  tfcw[36];
        __shared__ float  tb20[32];
        __shared__ float  tb21[32];
        __shared__ float  tfcb[8];
        __shared__ float  th3[8][8];
        __shared__ float  th4[8][8];
        __shared__ float2 th2[8][32];

        const int t = threadIdx.x;
        for (int i = t; i < 1024; i += 256) {
            int k2 = i >> 5, l = i & 31;
            tw_ih0[i] = (l < 24)
                ? make_float2(w2_ih0[l * 64 + 2 * k2], w2_ih0[l * 64 + 2 * k2 + 1])
                : make_float2(0.f, 0.f);
        }
        if (t < 192) {
            int k = t / 32, l = t & 31;
            tw_hh0[t] = (l < 24) ? w2_hh0[l * 6 + k] : 0.f;
            tw_ih1[t] = (l < 24) ? w2_ih1[l * 6 + k] : 0.f;
            tw_hh1[t] = (l < 24) ? w2_hh1[l * 6 + k] : 0.f;
        }
        if (t < 36) tfcw[t] = fc_w[t];
        if (t < 32) { tb20[t] = (t < 24) ? b2_0[t] : 0.f;
                      tb21[t] = (t < 24) ? b2_1[t] : 0.f; }
        if (t < 8)  tfcb[t] = (t < 6) ? fc_b[t] : 0.f;
        if (t < 64) { th3[t >> 3][t & 7] = 0.f; th4[t >> 3][t & 7] = 0.f; }
        __syncthreads();

        const int w = t >> 5;                 // warp -> batch slot
        const int l = t & 31;
        const int b = (blockIdx.x - 64) * 8 + w;
        const int* flg = &g_flag[512 + b];
        float c3 = 0.f, c4 = 0.f;
        float* outp = out + ((size_t)b << 10) * 6;

        for (int s = 0; s < 1024; s++) {
            // acquire h2(s) (published in batches of 8 steps)
            while (ldcg_i(flg) < s + 1) __nanosleep(100);
            __threadfence();
            th2[w][l] = ldcg2(reinterpret_cast<const float2*>(
                                 &g_h2[((size_t)b * 1024 + s) * 64]) + l);
            __syncwarp();

            // L3: gates[24] = b2_0 + W2ih0 @ h2 + W2hh0 @ h3
            const float2* h2p = th2[w];
            float2 a0 = make_float2(0.f, 0.f), a1 = make_float2(0.f, 0.f);
#pragma unroll
            for (int k2 = 0; k2 < 32; k2 += 2) {
                a0 = ffma2(tw_ih0[k2 * 32 + l],       h2p[k2],     a0);
                a1 = ffma2(tw_ih0[(k2 + 1) * 32 + l], h2p[k2 + 1], a1);
            }
            float acc = a0.x + a0.y + a1.x + a1.y + tb20[l];
#pragma unroll
            for (int k = 0; k < 6; k++) acc += tw_hh0[k * 32 + l] * th3[w][k];
            float vf = __shfl_sync(FULL_MASK, acc, (l + 6) & 31);
            float vg = __shfl_sync(FULL_MASK, acc, (l + 12) & 31);
            float vo = __shfl_sync(FULL_MASK, acc, (l + 18) & 31);
            if (l < 6) {
                float gi = sigf(acc), gf = sigf(vf);
                float gg = tanh_fast(vg), go = sigf(vo);
                c3 = gf * c3 + gi * gg;
                th3[w][l] = go * tanh_fast(c3);
            }
            __syncwarp();
            // L4
            float acc4 = tb21[l];
#pragma unroll
            for (int k = 0; k < 6; k++) {
                acc4 += tw_ih1[k * 32 + l] * th3[w][k];
                acc4 += tw_hh1[k * 32 + l] * th4[w][k];
            }
            float wf = __shfl_sync(FULL_MASK, acc4, (l + 6) & 31);
            float wg = __shfl_sync(FULL_MASK, acc4, (l + 12) & 31);
            float wo = __shfl_sync(FULL_MASK, acc4, (l + 18) & 31);
            __syncwarp();
            if (l < 6) {
                float gi = sigf(acc4), gf = sigf(wf);
                float gg = tanh_fast(wg), go = sigf(wo);
                c4 = gf * c4 + gi * gg;
                th4[w][l] = go * tanh_fast(c4);
            }
            __syncwarp();
            if (l < 6) {
                float o = tfcb[l];
#pragma unroll
                for (int k = 0; k < 6; k++) o += tfcw[l * 6 + k] * th4[w][k];
                outp[(size_t)s * 6 + l] = o;
            }
        }
        return;
    }

    // ================= scan branch: L1/L2 only, 3 barriers/step =================
    __shared__ float sh_h1[64];
    __shared__ float sh_h2[64];
    __shared__ float sh_pre[2][256];     // double-buffered by step parity

    const int t = threadIdx.x;
    const int b = blockIdx.x;
    const int yb = b * 8;

    float2 wA[32], wB[32], wC[32];
    {
        const float2* pa = reinterpret_cast<const float2*>(w1_hh0) + t * 32;
        const float2* pb = reinterpret_cast<const float2*>(w1_ih1) + t * 32;
        const float2* pc = reinterpret_cast<const float2*>(w1_hh1) + t * 32;
#pragma unroll
        for (int i = 0; i < 32; i++) { wA[i] = pa[i]; wB[i] = pb[i]; wC[i] = pc[i]; }
    }
    const float bias11 = b1_1[t];

    if (t < 64) { sh_h1[t] = 0.f; sh_h2[t] = 0.f; }

    // wait for chunk 0
    if (t == 0) {
        while (atomicAdd(&g_flag[yb], 0) < 2) __nanosleep(64);
        __threadfence();
    }
    __syncthreads();

    float c1 = 0.f, c2 = 0.f;
    const float* xg = g_xg + ((size_t)b << 10) * 256;
    float xg_next = ldcg(&xg[t]);

    for (int step = 0; step < 1024; step++) {
        const int pr = step & 1;

        if (((step + 1) & 127) == 0 && step < 1023) {
            if (t == 0) {
                int yc = yb + ((step + 1) >> 7);
                while (atomicAdd(&g_flag[yc], 0) < 2) __nanosleep(64);
                __threadfence();
            }
            __syncthreads();
        }
        float xg_cur = xg_next;
        if (step < 1023) xg_next = ldcg(&xg[(size_t)(step + 1) * 256 + t]);

        // --- P1: L1 pre-activations = Whh0 @ h1 + xg ---
        {
            float2 acc0 = make_float2(0.f, 0.f), acc1 = make_float2(0.f, 0.f);
            const float4* hp = reinterpret_cast<const float4*>(sh_h1);
#pragma unroll
            for (int k4 = 0; k4 < 16; k4 += 2) {
                float4 ha = hp[k4];
                float4 hb = hp[k4 + 1];
                acc0 = ffma2(wA[2 * k4 + 0], make_float2(ha.x, ha.y), acc0);
                acc1 = ffma2(wA[2 * k4 + 1], make_float2(ha.z, ha.w), acc1);
                acc0 = ffma2(wA[2 * k4 + 2], make_float2(hb.x, hb.y), acc0);
                acc1 = ffma2(wA[2 * k4 + 3], make_float2(hb.z, hb.w), acc1);
            }
            sh_pre[pr][t] = acc0.x + acc0.y + acc1.x + acc1.y + xg_cur;
        }
        __syncthreads();   // S1  (orders h2 STGs of prior steps for publish below)

        // publish h2 in batches of 8 steps (amortizes the gpu-scope fence;
        // tail consumers have ~2x throughput slack and tolerate the lag)
        if (t == 0 && step > 0 && (step & 7) == 0) {
            __threadfence();
            atomicMax(&g_flag[512 + b], step);
        }

        // --- P3: L1 cell (t<64) + Whh1 @ h2 partial (all) ---
        float p2;
        {
            if (t < 64) {
                float gi = sigf(sh_pre[pr][t]);
                float gf = sigf(sh_pre[pr][64 + t]);
                float gg = tanh_fast(sh_pre[pr][128 + t]);
                float go = sigf(sh_pre[pr][192 + t]);
                c1 = gf * c1 + gi * gg;
                sh_h1[t] = go * tanh_fast(c1);
            }
            float2 acc0 = make_float2(0.f, 0.f), acc1 = make_float2(0.f, 0.f);
            const float4* hp = reinterpret_cast<const float4*>(sh_h2);
#pragma unroll
            for (int k4 = 0; k4 < 16; k4 += 2) {
                float4 ha = hp[k4];
                float4 hb = hp[k4 + 1];
                acc0 = ffma2(wC[2 * k4 + 0], make_float2(ha.x, ha.y), acc0);
                acc1 = ffma2(wC[2 * k4 + 1], make_float2(ha.z, ha.w), acc1);
                acc0 = ffma2(wC[2 * k4 + 2], make_float2(hb.x, hb.y), acc0);
                acc1 = ffma2(wC[2 * k4 + 3], make_float2(hb.z, hb.w), acc1);
            }
            p2 = acc0.x + acc0.y + acc1.x + acc1.y;
        }
        __syncthreads();   // S2 (h1 new visible)

        // --- P5: L2 pre-activations = Wih1 @ h1_new + p2 + b ---
        {
            float2 acc0 = make_float2(0.f, 0.f), acc1 = make_float2(0.f, 0.f);
            const float4* hp = reinterpret_cast<const float4*>(sh_h1);
#pragma unroll
            for (int k4 = 0; k4 < 16; k4 += 2) {
                float4 ha = hp[k4];
                float4 hb = hp[k4 + 1];
                acc0 = ffma2(wB[2 * k4 + 0], make_float2(ha.x, ha.y), acc0);
                acc1 = ffma2(wB[2 * k4 + 1], make_float2(ha.z, ha.w), acc1);
                acc0 = ffma2(wB[2 * k4 + 2], make_float2(hb.x, hb.y), acc0);
                acc1 = ffma2(wB[2 * k4 + 3], make_float2(hb.z, hb.w), acc1);
            }
            sh_pre[pr][t] = acc0.x + acc0.y + acc1.x + acc1.y + p2 + bias11;
        }
        __syncthreads();   // S3

        // --- P7: L2 cell (t<64); overlaps next step's P1 (no barrier) ---
        if (t < 64) {
            float gi = sigf(sh_pre[pr][t]);
            float gf = sigf(sh_pre[pr][64 + t]);
            float gg = tanh_fast(sh_pre[pr][128 + t]);
            float go = sigf(sh_pre[pr][192 + t]);
            c2 = gf * c2 + gi * gg;
            float h2n = go * tanh_fast(c2);
            sh_h2[t] = h2n;
            stcg(&g_h2[((size_t)b * 1024 + step) * 64 + t], h2n);
        }
        // no S4: P1' writes sh_pre[pr^1], reads sh_h1 only; S1' orders h2.
    }
    __syncthreads();
    if (t == 0) {
        __threadfence();
        atomicMax(&g_flag[512 + b], 1024);
    }
}

// ---------------------------------------------------------------------------
extern "C" void kernel_launch(void* const* d_in, const int* in_sizes, int n_in,
                              void* d_out, int out_size) {
    const float* x      = (const float*)d_in[0];
    const float* w1_ih0 = (const float*)d_in[1];
    const float* w1_hh0 = (const float*)d_in[2];
    const float* b1_0   = (const float*)d_in[3];
    const float* w1_ih1 = (const float*)d_in[4];
    const float* w1_hh1 = (const float*)d_in[5];
    const float* b1_1   = (const float*)d_in[6];
    const float* w2_ih0 = (const float*)d_in[7];
    const float* w2_hh0 = (const float*)d_in[8];
    const float* b2_0   = (const float*)d_in[9];
    const float* w2_ih1 = (const float*)d_in[10];
    const float* w2_hh1 = (const float*)d_in[11];
    const float* b2_1   = (const float*)d_in[12];
    const float* fc_w   = (const float*)d_in[13];
    const float* fc_b   = (const float*)d_in[14];
    float* out = (float*)d_out;

    // reset completion flags (graph-capturable memset node)
    void* flag_ptr = nullptr;
    cudaGetSymbolAddress(&flag_ptr, g_flag);
    cudaMemsetAsync(flag_ptr, 0, 576 * sizeof(int));

    fused_kernel<<<72 + 1024, 256>>>(x, w1_ih0, w1_hh0, b1_0,
                                     w1_ih1, w1_hh1, b1_1,
                                     w2_ih0, w2_hh0, b2_0,
                                     w2_ih1, w2_hh1, b2_1,
                                     fc_w, fc_b, out);
}